// round 17
// baseline (speedup 1.0000x reference)
#include <cuda_runtime.h>
#include <cuda_fp16.h>

#define T_LEN 1024
#define BATCH 4
#define EMB   1024
#define NH    16
#define HD    64
#define BH    (BATCH*NH)   // 64
#define NREL  33           // 2L+1

// Scratch (static device arrays: allocation-free per harness rules)
__device__ __half g_q[BH * T_LEN * HD];        // fp16, pre-scaled by 0.125*log2e
__device__ __half g_k[BH * T_LEN * HD];        // fp16
__device__ __half g_v[BH * HD * T_LEN];        // fp16, TRANSPOSED [bh][d][t]
__device__ __half g_attn[T_LEN * BATCH * EMB]; // fp16, [t*4+b][e]
__device__ __half g_qin[4096 * 1024];          // fp16(query)
__device__ __half g_win[3072 * 1024];          // fp16(w_in)
__device__ __half g_wout[1024 * 1024];         // fp16(w_out)

__device__ __forceinline__ float ex2(float x) {
    float y;
    asm("ex2.approx.ftz.f32 %0, %1;" : "=f"(y) : "f"(x));
    return y;
}

// m16n8k16 fp16 -> fp32. c aliases d.
__device__ __forceinline__ void mma16(float* c, const unsigned* a, const unsigned* b) {
    asm volatile(
        "mma.sync.aligned.m16n8k16.row.col.f32.f16.f16.f32 "
        "{%0,%1,%2,%3}, {%4,%5,%6,%7}, {%8,%9}, {%0,%1,%2,%3};\n"
        : "+f"(c[0]), "+f"(c[1]), "+f"(c[2]), "+f"(c[3])
        : "r"(a[0]), "r"(a[1]), "r"(a[2]), "r"(a[3]), "r"(b[0]), "r"(b[1]));
}

__device__ __forceinline__ unsigned smem_u32(const void* p) {
    return (unsigned)__cvta_generic_to_shared(p);
}

__device__ __forceinline__ void ldsm4(unsigned* d, unsigned addr) {
    asm volatile(
        "ldmatrix.sync.aligned.m8n8.x4.shared.b16 {%0,%1,%2,%3}, [%4];"
        : "=r"(d[0]), "=r"(d[1]), "=r"(d[2]), "=r"(d[3]) : "r"(addr));
}

__device__ __forceinline__ void cpa16(unsigned dst, const void* src) {
    asm volatile("cp.async.cg.shared.global [%0], [%1], 16;"
                 :: "r"(dst), "l"(src));
}

// ---------------------------------------------------------------------------
// Fused fp32 -> fp16(rn) pre-conversion for query, w_in, w_out (one launch).
// ---------------------------------------------------------------------------
__global__ void __launch_bounds__(256)
cvt_all(const float* __restrict__ q, const float* __restrict__ wi,
        const float* __restrict__ wo)
{
    const int i = blockIdx.x * 256 + threadIdx.x;
    const float* src;
    __half* dst;
    int off;
    if (i < 1048576)      { src = q;  dst = g_qin;  off = i; }
    else if (i < 1835008) { src = wi; dst = g_win;  off = i - 1048576; }
    else                  { src = wo; dst = g_wout; off = i - 1835008; }
    float4 v = ((const float4*)src)[off];
    ((__half2*)dst)[2 * off]     = __floats2half2_rn(v.x, v.y);
    ((__half2*)dst)[2 * off + 1] = __floats2half2_rn(v.z, v.w);
}

// ---------------------------------------------------------------------------
// FP16 TC GEMM (validated round-16): block 128x128, K-chunk 64 halves,
// 8 warps (32m x 64n), cp.async 3-stage ring (one barrier per chunk),
// software-pipelined fragment loads, 2 CTAs/SM.
// mode 0: scatter q/k/v fp16 (q scaled by 0.125*log2e, V transposed).
// mode 1: write fp32 Cout.
// ---------------------------------------------------------------------------
#define GSTG (128 * 36)          // words per matrix per stage
#define GSTGB (GSTG * 4)

__global__ void __launch_bounds__(256, 2)
gemm_tc(const __half* __restrict__ A, const __half* __restrict__ B,
        const float* __restrict__ bias, float* __restrict__ Cout,
        int M, int N, int K, int mode)
{
    extern __shared__ unsigned sh[];
    unsigned* As = sh;               // [3][128*36] words
    unsigned* Bs = sh + 3 * GSTG;

    const int tid  = threadIdx.x;
    const int lane = tid & 31;
    const int warp = tid >> 5;
    const int wm   = (warp & 3) * 32;
    const int wn   = (warp >> 2) * 64;
    const int row0 = blockIdx.y * 128;
    const int col0 = blockIdx.x * 128;

    const int lrow = lane & 7;
    const int lb3  = (lane >> 3) & 1;
    const int lb4  = lane >> 4;
    unsigned aAddr[2], bAddr[4];
#pragma unroll
    for (int mt = 0; mt < 2; mt++)
        aAddr[mt] = smem_u32(&As[(wm + mt * 16 + lrow + lb3 * 8) * 36 + lb4 * 4]);
#pragma unroll
    for (int np = 0; np < 4; np++)
        bAddr[np] = smem_u32(&Bs[(wn + np * 16 + lb4 * 8 + lrow) * 36 + lb3 * 4]);

    const unsigned aSm = smem_u32(As);
    const unsigned bSm = smem_u32(Bs);

    float acc[2][8][4];
#pragma unroll
    for (int mt = 0; mt < 2; mt++)
#pragma unroll
        for (int nt = 0; nt < 8; nt++)
#pragma unroll
            for (int f = 0; f < 4; f++) acc[mt][nt][f] = 0.0f;

    const __half* aP = A + (size_t)row0 * K;
    const __half* bP = B + (size_t)col0 * K;

    auto issue = [&](int k0, int st) {
        const unsigned aDst = aSm + (unsigned)st * GSTGB;
        const unsigned bDst = bSm + (unsigned)st * GSTGB;
#pragma unroll
        for (int it = 0; it < 4; it++) {
            const int i = tid + 256 * it;
            const int r = i >> 3, seg = i & 7;
            const unsigned doff = (unsigned)(r * 36 + seg * 4) * 4;
            cpa16(aDst + doff, aP + (size_t)r * K + k0 + seg * 8);
            cpa16(bDst + doff, bP + (size_t)r * K + k0 + seg * 8);
        }
        asm volatile("cp.async.commit_group;");
    };

    const int nC = K >> 6;
    issue(0, 0);
    if (nC > 1) issue(64, 1);

    for (int c = 0; c < nC; c++) {
        const int st = c % 3;
        const unsigned soff = (unsigned)st * GSTGB;

        if (c + 1 < nC) asm volatile("cp.async.wait_group 1;");
        else            asm volatile("cp.async.wait_group 0;");
        __syncthreads();     // chunk c resident; stage (c+2)%3 fully consumed

        if (c + 2 < nC) issue((c + 2) * 64, (c + 2) % 3);

        // 16 flattened (ks,np) steps, fragment loads pipelined 1 step ahead.
        unsigned aF[2][2][4];     // [ks&1][mt][4]
        unsigned bF[2][4];        // [s&1][4]
        ldsm4(aF[0][0], aAddr[0] + soff);
        ldsm4(aF[0][1], aAddr[1] + soff);
        ldsm4(bF[0],    bAddr[0] + soff);
#pragma unroll
        for (int s = 0; s < 16; s++) {
            const int ks = s >> 2, np = s & 3;
            const int ns = s + 1;
            if (ns < 16) {
                const int nks = ns >> 2, nnp = ns & 3;
                const unsigned ko = soff + nks * 32;
                if (nnp == 0) {
                    ldsm4(aF[nks & 1][0], aAddr[0] + ko);
                    ldsm4(aF[nks & 1][1], aAddr[1] + ko);
                }
                ldsm4(bF[ns & 1], bAddr[nnp] + ko);
            }
            const unsigned* a0 = aF[ks & 1][0];
            const unsigned* a1 = aF[ks & 1][1];
            const unsigned* bc = bF[s & 1];
            mma16(acc[0][2 * np],     a0, &bc[0]);
            mma16(acc[1][2 * np],     a1, &bc[0]);
            mma16(acc[0][2 * np + 1], a0, &bc[2]);
            mma16(acc[1][2 * np + 1], a1, &bc[2]);
        }
    }

    // epilogue (paired cc stores: half2 for q/k, float2 for Cout)
    const int q4 = lane & 3;
    const int g8 = lane >> 2;
#pragma unroll
    for (int mt = 0; mt < 2; mt++) {
#pragma unroll
        for (int rr = 0; rr < 2; rr++) {
            const int m = row0 + wm + mt * 16 + g8 + rr * 8;
#pragma unroll
            for (int nt = 0; nt < 8; nt++) {
                const int n0 = col0 + wn + nt * 8 + 2 * q4;
                const float v0 = acc[mt][nt][rr * 2]     + bias[n0];
                const float v1 = acc[mt][nt][rr * 2 + 1] + bias[n0 + 1];
                if (mode == 0) {
                    const int sec = n0 >> 10;
                    const int e = n0 & 1023;
                    const int h = e >> 6, d = e & 63;  // d even; d,d+1 same head
                    const int t = m >> 2, b = m & 3;
                    const int bh = b * NH + h;
                    if (sec == 0) {  // 0.125 * log2(e)
                        *(__half2*)&g_q[(bh * T_LEN + t) * HD + d] =
                            __floats2half2_rn(v0 * 0.18033688f, v1 * 0.18033688f);
                    } else if (sec == 1) {
                        *(__half2*)&g_k[(bh * T_LEN + t) * HD + d] =
                            __floats2half2_rn(v0, v1);
                    } else {  // V transposed: [bh][d][t] (scalar, strided)
                        g_v[((size_t)bh * HD + d) * T_LEN + t]       = __float2half_rn(v0);
                        g_v[((size_t)bh * HD + d + 1) * T_LEN + t]   = __float2half_rn(v1);
                    }
                } else {
                    *(float2*)&Cout[(size_t)m * N + n0] = make_float2(v0, v1);
                }
            }
        }
    }
}

// ---------------------------------------------------------------------------
// FP16 flash attention: 128-row q-tiles, 8 warps x 16 rows, double-buffered
// K/V smem (one barrier per k-tile), hoisted Q frags, PIPELINED K/V fragment
// rings in QK^T and PV loops (1-ahead), base-2 softmax, saturation fast path,
// MMA qr prologue, register-resident P.
// grid = (8 q-tiles, 64 heads), 256 threads. 71.8KB smem.
// ---------------------------------------------------------------------------
__global__ void __launch_bounds__(256)
attn_tc(const float* __restrict__ relk)
{
    extern __shared__ float sm[];
    unsigned* Qs = (unsigned*)sm;             // [128][36]w rows=t, cols=d halves
    unsigned* Ks = Qs + 128 * 36;             // [2][64][36]w rows=s, cols=d
    unsigned* Vs = Ks + 2 * 64 * 36;          // [2][64][36]w rows=d, cols=s
    float* qrs   = (float*)(Vs + 2 * 64 * 36);// [128][33] fp32
    unsigned* Rs = Ks;                        // rel overlay on Ks[0] (consumed first)

    const int tid  = threadIdx.x;
    const int lane = tid & 31;
    const int warp = tid >> 5;                // 0..7
    const int q4   = lane & 3;
    const int g8   = lane >> 2;               // 0..7
    const int bh   = blockIdx.y;
    const int tq0  = blockIdx.x * 128;
    const int m0   = warp * 16;

    const int lrow = lane & 7;
    const int lb3  = (lane >> 3) & 1;
    const int lb4  = lane >> 4;
    const unsigned qAddr = smem_u32(&Qs[(m0 + lrow + lb3 * 8) * 36 + lb4 * 4]);
    unsigned kAddr[2][4], vAddr[2][4], relAddr[3];
#pragma unroll
    for (int st = 0; st < 2; st++)
#pragma unroll
        for (int np = 0; np < 4; np++) {
            kAddr[st][np] = smem_u32(&Ks[(st * 64 + np * 16 + lb4 * 8 + lrow) * 36 + lb3 * 4]);
            vAddr[st][np] = smem_u32(&Vs[(st * 64 + np * 16 + lb4 * 8 + lrow) * 36 + lb3 * 4]);
        }
#pragma unroll
    for (int np = 0; np < 3; np++)
        relAddr[np] = smem_u32(&Rs[(np * 16 + lb4 * 8 + lrow) * 36 + lb3 * 4]);

    // load Q tile (128x64 halves = 1024 uint4)
    {
        const uint4* qb = (const uint4*)(g_q + (size_t)(bh * T_LEN + tq0) * HD);
#pragma unroll
        for (int i = tid; i < 1024; i += 256)
            *(uint4*)&Qs[(i >> 3) * 36 + (i & 7) * 4] = qb[i];
    }
    // relation keys (fp16) into Rs (= Ks[0] region); zero first
    for (int i = tid; i < 64 * 36; i += 256) Rs[i] = 0u;
    __syncthreads();
    {
        __half* relsH = (__half*)Rs;
        for (int i = tid; i < NREL * 64; i += 256) {
            const int j = i >> 6, d = i & 63;
            relsH[j * 72 + d] = __float2half_rn(relk[j * EMB + d]);
        }
    }
    __syncthreads();

    // hoist Q fragments (loop-invariant) and run qr prologue
    unsigned qf[4][4];
#pragma unroll
    for (int ks = 0; ks < 4; ks++) ldsm4(qf[ks], qAddr + ks * 32);

    {
        float sq[6][4];
#pragma unroll
        for (int nt = 0; nt < 6; nt++)
#pragma unroll
            for (int f = 0; f < 4; f++) sq[nt][f] = 0.0f;
#pragma unroll
        for (int ks = 0; ks < 4; ks++) {
#pragma unroll
            for (int np = 0; np < 3; np++) {
                unsigned bf[4];
                ldsm4(bf, relAddr[np] + ks * 32);
                mma16(sq[2 * np],     qf[ks], &bf[0]);
                mma16(sq[2 * np + 1], qf[ks], &bf[2]);
            }
        }
#pragma unroll
        for (int rid = 0; rid < 2; rid++) {
            const int rloc = m0 + rid * 8 + g8;
#pragma unroll
            for (int nt = 0; nt < 6; nt++)
#pragma unroll
                for (int cc = 0; cc < 2; cc++) {
                    const int j = nt * 8 + 2 * q4 + cc;
                    if (j < NREL) qrs[rloc * NREL + j] = sq[nt][rid * 2 + cc];
                }
        }
    }

    const __half* kbase = g_k + (size_t)bh * T_LEN * HD;   // [t][d]
    const __half* vbase = g_v + (size_t)bh * HD * T_LEN;   // [d][t]

    // prefetch tile 0 (512 uint4 per matrix, 2 per thread)
    uint4 pk[2], pv[2];
#pragma unroll
    for (int it = 0; it < 2; it++) {
        const int i = tid + 256 * it;
        const int r = i >> 3, c8 = (i & 7) * 8;
        pk[it] = *(const uint4*)(kbase + (size_t)r * HD + c8);
        pv[it] = *(const uint4*)(vbase + (size_t)r * T_LEN + c8);
    }

    float o[8][4];
#pragma unroll
    for (int nt = 0; nt < 8; nt++)
#pragma unroll
        for (int f = 0; f < 4; f++) o[nt][f] = 0.0f;
    float mrow[2] = {-1e30f, -1e30f};
    float lrw[2]  = {0.0f, 0.0f};

    __syncthreads();   // all warps done reading Rs; qr writes complete

    // store tile 0 into stage 0 (overwrites Rs region)
#pragma unroll
    for (int it = 0; it < 2; it++) {
        const int i = tid + 256 * it;
        const int r = i >> 3, w4 = (i & 7) * 4;
        *(uint4*)&Ks[r * 36 + w4] = pk[it];
        *(uint4*)&Vs[r * 36 + w4] = pv[it];
    }
    __syncthreads();   // stage 0 valid

    for (int kt = 0; kt < 16; kt++) {
        const int s0 = kt * 64;
        const int st = kt & 1;

        // prefetch tile kt+1 into registers
        if (kt + 1 < 16) {
            const __half* kb = kbase + (size_t)(s0 + 64) * HD;
#pragma unroll
            for (int it = 0; it < 2; it++) {
                const int i = tid + 256 * it;
                const int r = i >> 3, c8 = (i & 7) * 8;
                pk[it] = *(const uint4*)(kb + (size_t)r * HD + c8);
                pv[it] = *(const uint4*)(vbase + (size_t)r * T_LEN + s0 + 64 + c8);
            }
        }

        // S = Q @ K^T : 16 flattened steps, K-frag ring 1-ahead
        float s[8][4];
#pragma unroll
        for (int nt = 0; nt < 8; nt++)
#pragma unroll
            for (int f = 0; f < 4; f++) s[nt][f] = 0.0f;

        {
            unsigned bf[2][4];
            ldsm4(bf[0], kAddr[st][0]);
#pragma unroll
            for (int s2 = 0; s2 < 16; s2++) {
                const int ks = s2 >> 2, np = s2 & 3;
                if (s2 + 1 < 16) {
                    const int nks = (s2 + 1) >> 2, nnp = (s2 + 1) & 3;
                    ldsm4(bf[(s2 + 1) & 1], kAddr[st][nnp] + nks * 32);
                }
                const unsigned* bc = bf[s2 & 1];
                mma16(s[2 * np],     qf[ks], &bc[0]);
                mma16(s[2 * np + 1], qf[ks], &bc[2]);
            }
        }

        // bias + online softmax, base-2; pack P directly into A-fragments
        unsigned ph[2][8];
#pragma unroll
        for (int rid = 0; rid < 2; rid++) {
            const int rloc = m0 + rid * 8 + g8;
            const int rg = tq0 + rloc;
            const float* qr = &qrs[rloc * NREL];
            float vals[16];
            float mx = -1e30f;
            if (s0 - rg >= 16) {               // whole tile right-saturated
                const float b32 = qr[32];
#pragma unroll
                for (int nt = 0; nt < 8; nt++)
#pragma unroll
                    for (int cc = 0; cc < 2; cc++) {
                        float v = s[nt][rid * 2 + cc] + b32;
                        vals[nt * 2 + cc] = v;
                        mx = fmaxf(mx, v);
                    }
            } else if (rg - s0 >= 79) {        // whole tile left-saturated
                const float b0 = qr[0];
#pragma unroll
                for (int nt = 0; nt < 8; nt++)
#pragma unroll
                    for (int cc = 0; cc < 2; cc++) {
                        float v = s[nt][rid * 2 + cc] + b0;
                        vals[nt * 2 + cc] = v;
                        mx = fmaxf(mx, v);
                    }
            } else {
#pragma unroll
                for (int nt = 0; nt < 8; nt++)
#pragma unroll
                    for (int cc = 0; cc < 2; cc++) {
                        const int sg = s0 + nt * 8 + 2 * q4 + cc;
                        int delta = min(max(sg - rg, -16), 16) + 16;
                        float v = s[nt][rid * 2 + cc] + qr[delta];
                        vals[nt * 2 + cc] = v;
                        mx = fmaxf(mx, v);
                    }
            }
            mx = fmaxf(mx, __shfl_xor_sync(0xffffffffu, mx, 1));
            mx = fmaxf(mx, __shfl_xor_sync(0xffffffffu, mx, 2));
            const float mnew = fmaxf(mrow[rid], mx);
            const float alpha = ex2(mrow[rid] - mnew);
            float rs = 0.0f;
#pragma unroll
            for (int j = 0; j < 16; j++) {
                vals[j] = ex2(vals[j] - mnew);
                rs += vals[j];
            }
            rs += __shfl_xor_sync(0xffffffffu, rs, 1);
            rs += __shfl_xor_sync(0xffffffffu, rs, 2);
            lrw[rid] = lrw[rid] * alpha + rs;
            mrow[rid] = mnew;
#pragma unroll
            for (int nt = 0; nt < 8; nt++) {
                o[nt][rid * 2]     *= alpha;
                o[nt][rid * 2 + 1] *= alpha;
            }
#pragma unroll
            for (int j = 0; j < 8; j++) {
                __half2 h = __floats2half2_rn(vals[2 * j], vals[2 * j + 1]);
                ph[rid][j] = *(unsigned*)&h;
            }
        }

        // O += P @ V : 16 flattened steps, V-frag ring 1-ahead
        {
            unsigned vf[2][4];
            ldsm4(vf[0], vAddr[st][0]);
#pragma unroll
            for (int s2 = 0; s2 < 16; s2++) {
                const int ks = s2 >> 2, np = s2 & 3;
                if (s2 + 1 < 16) {
                    const int nks = (s2 + 1) >> 2, nnp = (s2 + 1) & 3;
                    ldsm4(vf[(s2 + 1) & 1], vAddr[st][nnp] + nks * 32);
                }
                unsigned a[4];
                a[0] = ph[0][2 * ks];
                a[1] = ph[1][2 * ks];
                a[2] = ph[0][2 * ks + 1];
                a[3] = ph[1][2 * ks + 1];
                const unsigned* vc = vf[s2 & 1];
                mma16(o[2 * np],     a, &vc[0]);
                mma16(o[2 * np + 1], a, &vc[2]);
            }
        }

        // store prefetched tile kt+1 into alternate stage; ONE barrier per kt
        if (kt + 1 < 16) {
            const int sn = st ^ 1;
#pragma unroll
            for (int it = 0; it < 2; it++) {
                const int i = tid + 256 * it;
                const int r = i >> 3, w4 = (i & 7) * 4;
                *(uint4*)&Ks[(sn * 64 + r) * 36 + w4] = pk[it];
                *(uint4*)&Vs[(sn * 64 + r) * 36 + w4] = pv[it];
            }
            __syncthreads();   // stage sn visible; all done reading stage st
        }
    }

    // write attn (fp16) in [t][b][e] layout
    const int b = bh >> 4, h = bh & 15;
#pragma unroll
    for (int rid = 0; rid < 2; rid++) {
        const int t = tq0 + m0 + rid * 8 + g8;
        const float inv = 1.0f / lrw[rid];
#pragma unroll
        for (int nt = 0; nt < 8; nt++) {
            const int d = nt * 8 + 2 * q4;
            *(__half2*)&g_attn[(size_t)(t * BATCH + b) * EMB + h * HD + d] =
                __floats2half2_rn(o[nt][rid * 2] * inv, o[nt][rid * 2 + 1] * inv);
        }
    }
}

// ---------------------------------------------------------------------------
extern "C" void kernel_launch(void* const* d_in, const int* in_sizes, int n_in,
                              void* d_out, int out_size)
{
    (void)in_sizes; (void)n_in; (void)out_size;
    const float* query = (const float*)d_in[0];   // [T,B,E]
    const float* w_in  = (const float*)d_in[1];   // [3E,E]
    const float* b_in  = (const float*)d_in[2];   // [3E]
    const float* relk  = (const float*)d_in[3];   // [33,E]
    const float* w_out = (const float*)d_in[4];   // [E,E]
    const float* b_out = (const float*)d_in[5];   // [E]
    float* out = (float*)d_out;                   // [T,B,E]

    __half *qin, *win, *wout, *attn_ptr;
    cudaGetSymbolAddress((void**)&qin,  g_qin);
    cudaGetSymbolAddress((void**)&win,  g_win);
    cudaGetSymbolAddress((void**)&wout, g_wout);
    cudaGetSymbolAddress((void**)&attn_ptr, g_attn);

    // 0) one-time fp32 -> fp16 pre-conversion (single fused launch)
    cvt_all<<<8192, 256>>>(query, w_in, w_out);

    const size_t gemm_smem = (size_t)6 * GSTG * sizeof(unsigned);  // 110592 B
    cudaFuncSetAttribute(gemm_tc,
                         cudaFuncAttributeMaxDynamicSharedMemorySize,
                         (int)gemm_smem);

    // 1) fused QKV projection -> fp16 head-major q/k/v (V transposed)
    gemm_tc<<<dim3(24, 32), 256, gemm_smem>>>(
        qin, win, b_in, nullptr, 4096, 3072, 1024, 0);

    // 2) flash attention with relative bias (128-row q-tiles, 2-stage K/V)
    const size_t attn_smem =
        (size_t)(128 * 36 + 4 * 64 * 36 + 128 * NREL) * sizeof(unsigned);  // 72192 B
    cudaFuncSetAttribute(attn_tc,
                         cudaFuncAttributeMaxDynamicSharedMemorySize,
                         (int)attn_smem);
    attn_tc<<<dim3(8, 64), 256, attn_smem>>>(relk);

    // 3) output projection (writes fp32 final output)
    gemm_tc<<<dim3(8, 32), 256, gemm_smem>>>(
        attn_ptr, wout, b_out, out, 4096, 1024, 1024, 1);
}